// round 12
// baseline (speedup 1.0000x reference)
#include <cuda_runtime.h>
#include <math.h>

#define BATCHN 2048
#define SEQN   512
#define INPN   128
#define HIDN   256
#define OUTN   64
#define KTOT   384
#define ROWS   16
#define NPROD  128                 // producer CTAs (16 rows each)
#define NCONS  20                  // consumer CTAs
#define GRIDN  (NPROD + NCONS)     // 148: one CTA per SM
#define NTHR   512
#define CSS    20                  // producer cs row stride (floats)
#define SHP    66                  // consumer sh row pad
#define NTILE  (32 * SEQN)         // (2048/64) row-groups x 512 timesteps
#define PUBM   31                  // publish progress every 32 steps
#define FEPS   1e-8f

typedef unsigned long long u64t;

__device__ float g_Wcat[KTOT * HIDN];                   // [384][256] lambda-folded
__device__ float g_H[(size_t)BATCHN * SEQN * HIDN];     // h history (1 GB scratch)
__device__ int      g_prog[NPROD];                      // steps completed per producer
__device__ unsigned g_ticket;                           // consumer work tickets

__device__ __forceinline__ u64t dup2(float a) {
    u64t r; asm("mov.b64 %0, {%1, %1};" : "=l"(r) : "f"(a)); return r;
}
__device__ __forceinline__ void ffma2(u64t& d, u64t a, u64t b) {
    asm("fma.rn.f32x2 %0, %1, %2, %0;" : "+l"(d) : "l"(a), "l"(b));
}
__device__ __forceinline__ float lo2(u64t v) { return __uint_as_float((unsigned)v); }
__device__ __forceinline__ float hi2(u64t v) { return __uint_as_float((unsigned)(v >> 32)); }
__device__ __forceinline__ int ld_acq(const int* p) {
    int v; asm volatile("ld.global.acquire.gpu.b32 %0, [%1];" : "=r"(v) : "l"(p)); return v;
}

__global__ void prep_kernel(const float* __restrict__ Win, const float* __restrict__ Wrec,
                            const float* __restrict__ li,  const float* __restrict__ lr) {
    int k = blockIdx.x, j = threadIdx.x;
    g_Wcat[k * HIDN + j] = (k < HIDN) ? lr[j] * Wrec[k * HIDN + j]
                                      : li[j] * Win[(k - HIDN) * HIDN + j];
}

__global__ void reset_kernel() {
    if (threadIdx.x < NPROD) g_prog[threadIdx.x] = 0;
    if (threadIdx.x == 0)    g_ticket = 0u;
}

// Consumer: out[b,t,c] = s_z * sum_j h[b,t,j] * Wout[j][c], tiles of 64 rows x 64 cols
__device__ void consume_tiles(float* sh, const float* __restrict__ Wout,
                              float sz, float* __restrict__ outp) {
    __shared__ unsigned s_n;
    const int tid = threadIdx.x;
    const int c = tid & 63, rg = tid >> 6;     // 8 row-groups of 8 rows
    for (;;) {
        if (tid == 0) s_n = atomicAdd(&g_ticket, 1u);
        __syncthreads();
        unsigned n = s_n;
        if (n >= NTILE) { __syncthreads(); return; }
        int t = n >> 5, mg = n & 31;           // rows mg*64 .. mg*64+63

        if (tid < 4) {                          // wait on the 4 producers we span
            const int* fp = &g_prog[mg * 4 + tid];
            while (ld_acq(fp) < t + 1) __nanosleep(256);
        }
        __syncthreads();

        // stage h tile transposed: sh[j][r]
        for (int idx = tid; idx < 64 * HIDN; idx += NTHR) {
            int r = idx >> 8, j = idx & 255;
            sh[j * SHP + r] = g_H[((size_t)(mg * 64 + r) * SEQN + t) * HIDN + j];
        }
        __syncthreads();

        u64t acc[4] = {0ull, 0ull, 0ull, 0ull};
        const float* wo = Wout + c;
#pragma unroll 4
        for (int j = 0; j < HIDN; ++j) {
            u64t b = dup2(wo[j * OUTN]);
            const float* hp = sh + j * SHP + rg * 8;
            u64t h0 = *(const u64t*)(hp);
            u64t h1 = *(const u64t*)(hp + 2);
            u64t h2 = *(const u64t*)(hp + 4);
            u64t h3 = *(const u64t*)(hp + 6);
            ffma2(acc[0], h0, b); ffma2(acc[1], h1, b);
            ffma2(acc[2], h2, b); ffma2(acc[3], h3, b);
        }
#pragma unroll
        for (int p = 0; p < 4; ++p) {
            int br = mg * 64 + rg * 8 + 2 * p;
            outp[((size_t)br * SEQN + t) * OUTN + c]       = sz * lo2(acc[p]);
            outp[((size_t)(br + 1) * SEQN + t) * OUTN + c] = sz * hi2(acc[p]);
        }
        __syncthreads();                       // sh + s_n reuse safe
    }
}

__global__ void __launch_bounds__(NTHR, 1) nlnn_fused(
    const float* __restrict__ x,         // [B,S,128]
    const float* __restrict__ h_init,    // [B,256]
    const float* __restrict__ alpha_raw, // [256]
    const float* __restrict__ Wout,      // [256,64]
    const float* __restrict__ s_z_p,
    float* __restrict__ outp,            // [B,S,64]
    float* __restrict__ hfin)
{
    extern __shared__ float smem[];
    const int tid = threadIdx.x;
    const float sz = s_z_p[0];

    if (blockIdx.x >= NPROD) {               // pure consumer CTA
        consume_tiles(smem, Wout, sz, outp);
        return;
    }

    // ---------------- producer: R4 recurrence body ----------------
    float* cs    = smem;                 // [384][CSS]: k<256 h, k>=256 x
    float* vpart = smem + KTOT * CSS;    // [4][16][256]

    const int b0 = blockIdx.x * ROWS;

    const int jg = tid & 63, rg = (tid >> 6) & 1, kg = tid >> 7;
    const int j4 = jg * 4, r0 = rg * 8;
    const int kbeg = kg * 96;

    const int w = tid >> 5, lane = tid & 31;

    float hh[8], al[8];
#pragma unroll
    for (int i = 0; i < 8; ++i) {
        int j = lane + 32 * i;
        hh[i] = h_init[(size_t)(b0 + w) * HIDN + j];
        al[i] = 1.0f / (1.0f + expf(-alpha_raw[j]));
        cs[j * CSS + w] = hh[i];
    }

    float xr[4];
#pragma unroll
    for (int i = 0; i < 4; ++i)
        xr[i] = x[(size_t)(b0 + w) * SEQN * INPN + lane + 32 * i];

    for (int t = 0; t < SEQN; ++t) {
#pragma unroll
        for (int i = 0; i < 4; ++i)
            cs[(HIDN + lane + 32 * i) * CSS + w] = xr[i];
        __syncthreads();                                   // S1: cs complete

        u64t acc[4][4];
#pragma unroll
        for (int p = 0; p < 4; ++p)
#pragma unroll
            for (int ccc = 0; ccc < 4; ++ccc) acc[p][ccc] = 0ull;

        const float* wp = g_Wcat + (size_t)kbeg * HIDN + j4;
        const float* cp = cs + kbeg * CSS + r0;
#pragma unroll 8
        for (int kk = 0; kk < 96; ++kk) {
            float4 wv = *(const float4*)(wp + (size_t)kk * HIDN);
            ulonglong2 ha = *(const ulonglong2*)(cp + kk * CSS);
            ulonglong2 hb = *(const ulonglong2*)(cp + kk * CSS + 4);
            u64t bx = dup2(wv.x), by = dup2(wv.y), bz = dup2(wv.z), bw = dup2(wv.w);
            ffma2(acc[0][0], ha.x, bx); ffma2(acc[0][1], ha.x, by);
            ffma2(acc[0][2], ha.x, bz); ffma2(acc[0][3], ha.x, bw);
            ffma2(acc[1][0], ha.y, bx); ffma2(acc[1][1], ha.y, by);
            ffma2(acc[1][2], ha.y, bz); ffma2(acc[1][3], ha.y, bw);
            ffma2(acc[2][0], hb.x, bx); ffma2(acc[2][1], hb.x, by);
            ffma2(acc[2][2], hb.x, bz); ffma2(acc[2][3], hb.x, bw);
            ffma2(acc[3][0], hb.y, bx); ffma2(acc[3][1], hb.y, by);
            ffma2(acc[3][2], hb.y, bz); ffma2(acc[3][3], hb.y, bw);
        }
        {
            float* vp = vpart + (size_t)(kg * ROWS + r0) * HIDN + j4;
#pragma unroll
            for (int p = 0; p < 4; ++p) {
                *(float4*)(vp + (size_t)(2 * p) * HIDN) =
                    make_float4(lo2(acc[p][0]), lo2(acc[p][1]), lo2(acc[p][2]), lo2(acc[p][3]));
                *(float4*)(vp + (size_t)(2 * p + 1) * HIDN) =
                    make_float4(hi2(acc[p][0]), hi2(acc[p][1]), hi2(acc[p][2]), hi2(acc[p][3]));
            }
        }
        __syncthreads();                                   // S2: partials ready

        float vv[8], ssq = 0.f, hsq = 0.f, dtr = 0.f;
#pragma unroll
        for (int i = 0; i < 8; ++i) {
            int j = lane + 32 * i;
            float s = vpart[(0 * ROWS + w) * HIDN + j]
                    + vpart[(1 * ROWS + w) * HIDN + j]
                    + vpart[(2 * ROWS + w) * HIDN + j]
                    + vpart[(3 * ROWS + w) * HIDN + j];
            vv[i] = s;
            ssq = fmaf(s, s, ssq);
            hsq = fmaf(hh[i], hh[i], hsq);
            dtr = fmaf(hh[i], s, dtr);
        }
#pragma unroll
        for (int d = 16; d > 0; d >>= 1) {
            ssq += __shfl_xor_sync(0xffffffffu, ssq, d);
            hsq += __shfl_xor_sync(0xffffffffu, hsq, d);
            dtr += __shfl_xor_sync(0xffffffffu, dtr, d);
        }
        float ninv = 1.0f / (sqrtf(ssq) + FEPS);
        float hinv = 1.0f / (sqrtf(hsq) + FEPS);
        float dot  = dtr * ninv * hinv;
        dot = fminf(fmaxf(dot, -1.0f + FEPS), 1.0f - FEPS);
        float theta  = acosf(dot);
        float st     = __sinf(theta);
        float inv_st = 1.0f / (st + FEPS);
        bool  mask   = (st > FEPS);

        float res[8], rsq = 0.f;
#pragma unroll
        for (int i = 0; i < 8; ++i) {
            float hn = vv[i] * ninv;
            float ht = hh[i] * hinv;
            float ct = __sinf((1.0f - al[i]) * theta) * inv_st;
            float cn = __sinf(al[i] * theta) * inv_st;
            float r  = fmaf(ct, ht, cn * hn);
            r = mask ? r : hn;
            res[i] = r;
            rsq = fmaf(r, r, rsq);
        }
#pragma unroll
        for (int d = 16; d > 0; d >>= 1)
            rsq += __shfl_xor_sync(0xffffffffu, rsq, d);
        float rinv = 1.0f / (sqrtf(rsq) + FEPS);

        float* hrow = g_H + ((size_t)(b0 + w) * SEQN + t) * HIDN;
#pragma unroll
        for (int i = 0; i < 8; ++i) {
            hh[i] = res[i] * rinv;
            cs[(lane + 32 * i) * CSS + w] = hh[i];
            hrow[lane + 32 * i] = hh[i];
        }

        if (t + 1 < SEQN) {
#pragma unroll
            for (int i = 0; i < 4; ++i)
                xr[i] = x[((size_t)(b0 + w) * SEQN + t + 1) * INPN + lane + 32 * i];
        }

        // publish progress every 32 steps (fence -> CCTL.IVALL, keep it rare)
        if ((t & PUBM) == PUBM) {
            __threadfence();
            __syncthreads();
            if (tid == 0)
                *((volatile int*)&g_prog[blockIdx.x]) = t + 1;
        }
    }

    if (hfin) {
#pragma unroll
        for (int i = 0; i < 8; ++i)
            hfin[(size_t)(b0 + w) * HIDN + lane + 32 * i] = hh[i];
    }

    __syncthreads();                           // smem reuse as consumer sh
    consume_tiles(smem, Wout, sz, outp);       // role switch: help drain out tiles
}

extern "C" void kernel_launch(void* const* d_in, const int* in_sizes, int n_in,
                              void* d_out, int out_size) {
    const float* x      = (const float*)d_in[0];
    const float* h_init = (const float*)d_in[1];
    const float* Win    = (const float*)d_in[2];
    const float* Wrec   = (const float*)d_in[3];
    const float* Wout   = (const float*)d_in[4];
    const float* li     = (const float*)d_in[5];
    const float* lr     = (const float*)d_in[6];
    const float* sz     = (const float*)d_in[7];
    const float* ar     = (const float*)d_in[8];

    float* outp = (float*)d_out;
    long long main_elems = (long long)BATCHN * SEQN * OUTN;
    float* hfin = nullptr;
    if ((long long)out_size >= main_elems + (long long)BATCHN * HIDN)
        hfin = outp + main_elems;

    int smem_prod = (KTOT * CSS + 4 * ROWS * HIDN) * (int)sizeof(float);   // 96 KB
    int smem_cons = (HIDN * SHP) * (int)sizeof(float);                     // 67.6 KB
    int smem_fused = smem_prod > smem_cons ? smem_prod : smem_cons;
    cudaFuncSetAttribute(nlnn_fused, cudaFuncAttributeMaxDynamicSharedMemorySize, smem_fused);

    prep_kernel<<<KTOT, HIDN>>>(Win, Wrec, li, lr);
    nlnn_fused<<<GRIDN, NTHR, smem_fused>>>(x, h_init, ar, Wout, sz, outp, hfin);
    reset_kernel<<<1, 256>>>();     // clear flags/ticket for next replay
    reset_kernel<<<1, 256>>>();     // pad
}

// round 14
// speedup vs baseline: 1.6729x; 1.6729x over previous
#include <cuda_runtime.h>
#include <math.h>

#define BATCHN 2048
#define SEQN   512
#define INPN   128
#define HIDN   256
#define OUTN   64
#define KTOT   384
#define NKT    24            // k-tiles of 16
#define ROWS   16
#define NTHR   512
#define AKS    136           // As per-ktile stride in u32 (128 + 8 pad)
#define VSTR   258           // vfin row stride (floats)
#define FEPS   1e-8f

typedef unsigned long long u64t;
typedef unsigned short u16t;

// weight fragments, lambda-folded, bf16 hi/lo planes, mma-fragment-major:
// index ((plane*NKT + kt)*32 + ntile)*32 + lane  -> u64 {b0,b1}
__device__ u64t  g_WB[2 * NKT * 32 * 32];
__device__ float g_H[(size_t)BATCHN * SEQN * HIDN];   // h history (1 GB scratch)

__device__ __forceinline__ u64t dup2(float a) {
    u64t r; asm("mov.b64 %0, {%1, %1};" : "=l"(r) : "f"(a)); return r;
}
__device__ __forceinline__ void ffma2(u64t& d, u64t a, u64t b) {
    asm("fma.rn.f32x2 %0, %1, %2, %0;" : "+l"(d) : "l"(a), "l"(b));
}
__device__ __forceinline__ float lo2(u64t v) { return __uint_as_float((unsigned)v); }
__device__ __forceinline__ float hi2(u64t v) { return __uint_as_float((unsigned)(v >> 32)); }

__device__ __forceinline__ u16t bf16h(float v) {
    u16t h; asm("cvt.rn.bf16.f32 %0, %1;" : "=h"(h) : "f"(v)); return h;
}
__device__ __forceinline__ float bf16f(u16t h) {        // exact bf16 -> f32
    return __uint_as_float(((unsigned)h) << 16);
}

__device__ __forceinline__ void mma16816(float* d, uint4 a, u64t b) {
    unsigned b0 = (unsigned)b, b1 = (unsigned)(b >> 32);
    asm volatile(
        "mma.sync.aligned.m16n8k16.row.col.f32.bf16.bf16.f32 "
        "{%0,%1,%2,%3},{%4,%5,%6,%7},{%8,%9},{%0,%1,%2,%3};"
        : "+f"(d[0]), "+f"(d[1]), "+f"(d[2]), "+f"(d[3])
        : "r"(a.x), "r"(a.y), "r"(a.z), "r"(a.w), "r"(b0), "r"(b1));
}

// full lambda-folded weight element W[k][n], k in [0,384)
__device__ __forceinline__ float wfull(int k, int n,
        const float* Win, const float* Wrec, const float* li, const float* lr) {
    return (k < HIDN) ? lr[n] * Wrec[k * HIDN + n]
                      : li[n] * Win[(k - HIDN) * HIDN + n];
}

// pack W into mma B-fragment layout, split bf16 hi/lo
__global__ void prep_kernel(const float* __restrict__ Win, const float* __restrict__ Wrec,
                            const float* __restrict__ li,  const float* __restrict__ lr) {
    int gid = blockIdx.x * blockDim.x + threadIdx.x;     // 0 .. 24576-1 (kt,nt,lane)
    int kt = gid >> 10, rem = gid & 1023;
    int nt = rem >> 5, l = rem & 31;
    if (kt >= NKT) return;
    int k0 = kt * 16 + (l & 3) * 2;
    int n  = nt * 8 + (l >> 2);
    float e[4];
    e[0] = wfull(k0, n, Win, Wrec, li, lr);
    e[1] = wfull(k0 + 1, n, Win, Wrec, li, lr);
    e[2] = wfull(k0 + 8, n, Win, Wrec, li, lr);
    e[3] = wfull(k0 + 9, n, Win, Wrec, li, lr);
    u16t hi[4], lo[4];
#pragma unroll
    for (int i = 0; i < 4; ++i) {
        hi[i] = bf16h(e[i]);
        lo[i] = bf16h(e[i] - bf16f(hi[i]));
    }
    u64t vhi = (u64t)((unsigned)hi[0] | ((unsigned)hi[1] << 16))
             | ((u64t)((unsigned)hi[2] | ((unsigned)hi[3] << 16)) << 32);
    u64t vlo = (u64t)((unsigned)lo[0] | ((unsigned)lo[1] << 16))
             | ((u64t)((unsigned)lo[2] | ((unsigned)lo[3] << 16)) << 32);
    int base = (kt * 32 + nt) * 32 + l;
    g_WB[base] = vhi;
    g_WB[NKT * 32 * 32 + base] = vlo;
}

__global__ void __launch_bounds__(NTHR, 1) nlnn_main(
    const float* __restrict__ x,         // [B,S,128]
    const float* __restrict__ h_init,    // [B,256]
    const float* __restrict__ alpha_raw, // [256]
    float* __restrict__ hfin)
{
    __shared__ unsigned As[2 * NKT * AKS];     // A fragments, hi plane then lo plane
    __shared__ float    vfin[ROWS * VSTR];     // GEMM result [16][256] padded

    const int tid  = threadIdx.x;
    const int b0   = blockIdx.x * ROWS;
    const int w    = tid >> 5, lane = tid & 31;   // warp w <-> batch row w & n-slice w
    const int nt0  = 2 * w;                       // warp's first n8-tile
    const int la4  = lane * 4;

    u16t* As16 = (u16t*)As;

    // ---- per-thread A-frag write offsets (row = w, k' = lane&15, const over i) ----
    const int k15   = lane & 15;
    const int tl    = (w & 7) * 4 + ((k15 & 7) >> 1);
    const int aidx  = ((w >> 3) & 1) + ((k15 >> 3) << 1);
    const int aoff  = tl * 8 + aidx * 2 + (k15 & 1);   // u16 offset within kt block
    const int ktb   = lane >> 4;                       // 0 or 1

    float hh[8], al[8];
#pragma unroll
    for (int i = 0; i < 8; ++i) {
        int j = lane + 32 * i;
        hh[i] = h_init[(size_t)(b0 + w) * HIDN + j];
        al[i] = 1.0f / (1.0f + expf(-alpha_raw[j]));
        int kt = ktb + 2 * i;                           // j>>4 == ktb + 2i
        u16t bh = bf16h(hh[i]);
        u16t bl = bf16h(hh[i] - bf16f(bh));
        As16[kt * (2 * AKS) + aoff] = bh;
        As16[(NKT + kt) * (2 * AKS) + aoff] = bl;
    }
    // stage x_0, prefetch x_1
    float xr[4];
#pragma unroll
    for (int i = 0; i < 4; ++i) {
        float xv = x[(size_t)(b0 + w) * SEQN * INPN + lane + 32 * i];
        int kt = 16 + ktb + 2 * i;
        u16t bh = bf16h(xv);
        u16t bl = bf16h(xv - bf16f(bh));
        As16[kt * (2 * AKS) + aoff] = bh;
        As16[(NKT + kt) * (2 * AKS) + aoff] = bl;
        xr[i] = x[((size_t)(b0 + w) * SEQN + 1) * INPN + lane + 32 * i];
    }
    __syncthreads();

    const u64t* __restrict__ WB = g_WB;

    for (int t = 0; t < SEQN; ++t) {
        // ---- GEMM: D[16 x 16cols] = [h,x] @ W, 3-product bf16 split ----
        float d0[4] = {0.f, 0.f, 0.f, 0.f};
        float d1[4] = {0.f, 0.f, 0.f, 0.f};
#pragma unroll
        for (int kt = 0; kt < NKT; ++kt) {
            uint4 ah = *(const uint4*)(As + kt * AKS + la4);
            uint4 alo = *(const uint4*)(As + (NKT + kt) * AKS + la4);
            int bi = (kt * 32 + nt0) * 32 + lane;
            u64t bh0 = WB[bi];
            u64t bl0 = WB[NKT * 1024 + bi];
            u64t bh1 = WB[bi + 32];
            u64t bl1 = WB[NKT * 1024 + bi + 32];
            mma16816(d0, ah, bh0);
            mma16816(d0, alo, bh0);
            mma16816(d0, ah, bl0);
            mma16816(d1, ah, bh1);
            mma16816(d1, alo, bh1);
            mma16816(d1, ah, bl1);
        }
        // scatter D to vfin: lane -> rows (lane>>2, +8), cols nt*8 + (lane&3)*2
        {
            int gr = lane >> 2;
            float* vf = vfin + gr * VSTR + nt0 * 8 + (lane & 3) * 2;
            *(float2*)(vf)             = make_float2(d0[0], d0[1]);
            *(float2*)(vf + 8 * VSTR)  = make_float2(d0[2], d0[3]);
            *(float2*)(vf + 8)         = make_float2(d1[0], d1[1]);
            *(float2*)(vf + 8 * VSTR + 8) = make_float2(d1[2], d1[3]);
        }
        __syncthreads();                   // S2: vfin ready, As reads done

        // ---- phase B: warp w owns row w (fp32 slerp, unchanged) ----
        float vv[8], ssq = 0.f, hsq = 0.f, dtr = 0.f;
#pragma unroll
        for (int i = 0; i < 8; ++i) {
            float s = vfin[w * VSTR + lane + 32 * i];
            vv[i] = s;
            ssq = fmaf(s, s, ssq);
            hsq = fmaf(hh[i], hh[i], hsq);
            dtr = fmaf(hh[i], s, dtr);
        }
#pragma unroll
        for (int d = 16; d > 0; d >>= 1) {
            ssq += __shfl_xor_sync(0xffffffffu, ssq, d);
            hsq += __shfl_xor_sync(0xffffffffu, hsq, d);
            dtr += __shfl_xor_sync(0xffffffffu, dtr, d);
        }
        float ninv = 1.0f / (sqrtf(ssq) + FEPS);
        float hinv = 1.0f / (sqrtf(hsq) + FEPS);
        float dot  = dtr * ninv * hinv;
        dot = fminf(fmaxf(dot, -1.0f + FEPS), 1.0f - FEPS);
        float theta  = acosf(dot);
        float st     = __sinf(theta);
        float inv_st = 1.0f / (st + FEPS);
        bool  mask   = (st > FEPS);

        float res[8], rsq = 0.f;
#pragma unroll
        for (int i = 0; i < 8; ++i) {
            float hn = vv[i] * ninv;
            float ht = hh[i] * hinv;
            float ct = __sinf((1.0f - al[i]) * theta) * inv_st;
            float cn = __sinf(al[i] * theta) * inv_st;
            float r  = fmaf(ct, ht, cn * hn);
            r = mask ? r : hn;
            res[i] = r;
            rsq = fmaf(r, r, rsq);
        }
#pragma unroll
        for (int d = 16; d > 0; d >>= 1)
            rsq += __shfl_xor_sync(0xffffffffu, rsq, d);
        float rinv = 1.0f / (sqrtf(rsq) + FEPS);

        float* hrow = g_H + ((size_t)(b0 + w) * SEQN + t) * HIDN;
#pragma unroll
        for (int i = 0; i < 8; ++i) {
            float h = res[i] * rinv;
            hh[i] = h;
            hrow[lane + 32 * i] = h;
            int kt = ktb + 2 * i;
            u16t bh = bf16h(h);
            u16t bl = bf16h(h - bf16f(bh));
            As16[kt * (2 * AKS) + aoff] = bh;
            As16[(NKT + kt) * (2 * AKS) + aoff] = bl;
        }
        // stage x_{t+1}, prefetch x_{t+2}
        {
            int tt = (t + 2 < SEQN) ? t + 2 : SEQN - 1;
#pragma unroll
            for (int i = 0; i < 4; ++i) {
                int kt = 16 + ktb + 2 * i;
                u16t bh = bf16h(xr[i]);
                u16t bl = bf16h(xr[i] - bf16f(bh));
                As16[kt * (2 * AKS) + aoff] = bh;
                As16[(NKT + kt) * (2 * AKS) + aoff] = bl;
                xr[i] = x[((size_t)(b0 + w) * SEQN + tt) * INPN + lane + 32 * i];
            }
        }
        __syncthreads();                   // S1: As (h_{t+1}, x_{t+1}) ready
    }

    if (hfin) {
#pragma unroll
        for (int i = 0; i < 8; ++i)
            hfin[(size_t)(b0 + w) * HIDN + lane + 32 * i] = hh[i];
    }
}

// out[row][c] = s_z * sum_j H[row][j]*Wout[j][c]  (fp32, unchanged from R4)
#define OB_ROWS 64
#define HSTR    68
__global__ void __launch_bounds__(256, 2) nlnn_out(
    const float* __restrict__ Wout, const float* __restrict__ s_z_p,
    float* __restrict__ outp)
{
    extern __shared__ float sh[];                     // [256][HSTR]
    const int tid = threadIdx.x;
    const size_t row0 = (size_t)blockIdx.x * OB_ROWS;

#pragma unroll 8
    for (int i = 0; i < OB_ROWS; ++i)
        sh[tid * HSTR + i] = g_H[(row0 + i) * HIDN + tid];
    __syncthreads();

    const int c = tid & 63, rb = (tid >> 6) * 16;
    const float sz = s_z_p[0];

    u64t acc[8];
#pragma unroll
    for (int p = 0; p < 8; ++p) acc[p] = 0ull;

#pragma unroll 4
    for (int j = 0; j < HIDN; ++j) {
        u64t b = dup2(Wout[j * OUTN + c]);
        const float* hp = sh + j * HSTR + rb;
        ulonglong2 hA = *(const ulonglong2*)(hp);
        ulonglong2 hB = *(const ulonglong2*)(hp + 4);
        ulonglong2 hC = *(const ulonglong2*)(hp + 8);
        ulonglong2 hD = *(const ulonglong2*)(hp + 12);
        ffma2(acc[0], hA.x, b); ffma2(acc[1], hA.y, b);
        ffma2(acc[2], hB.x, b); ffma2(acc[3], hB.y, b);
        ffma2(acc[4], hC.x, b); ffma2(acc[5], hC.y, b);
        ffma2(acc[6], hD.x, b); ffma2(acc[7], hD.y, b);
    }
#pragma unroll
    for (int p = 0; p < 8; ++p) {
        size_t r = row0 + rb + 2 * p;
        outp[r * OUTN + c]       = sz * lo2(acc[p]);
        outp[(r + 1) * OUTN + c] = sz * hi2(acc[p]);
    }
}

extern "C" void kernel_launch(void* const* d_in, const int* in_sizes, int n_in,
                              void* d_out, int out_size) {
    const float* x      = (const float*)d_in[0];
    const float* h_init = (const float*)d_in[1];
    const float* Win    = (const float*)d_in[2];
    const float* Wrec   = (const float*)d_in[3];
    const float* Wout   = (const float*)d_in[4];
    const float* li     = (const float*)d_in[5];
    const float* lr     = (const float*)d_in[6];
    const float* sz     = (const float*)d_in[7];
    const float* ar     = (const float*)d_in[8];

    float* outp = (float*)d_out;
    long long main_elems = (long long)BATCHN * SEQN * OUTN;
    float* hfin = nullptr;
    if ((long long)out_size >= main_elems + (long long)BATCHN * HIDN)
        hfin = outp + main_elems;

    int smem_out = (HIDN * HSTR) * (int)sizeof(float);
    cudaFuncSetAttribute(nlnn_out, cudaFuncAttributeMaxDynamicSharedMemorySize, smem_out);

    prep_kernel<<<96, 256>>>(Win, Wrec, li, lr);          // 24576 frags
    nlnn_main<<<BATCHN / ROWS, NTHR>>>(x, h_init, ar, hfin);
    nlnn_out<<<(BATCHN * SEQN) / OB_ROWS, 256, smem_out>>>(Wout, sz, outp);
}